// round 16
// baseline (speedup 1.0000x reference)
#include <cuda_runtime.h>
#include <cuda_fp16.h>
#include <cstdint>
#include <cstddef>

// ---------------------------------------------------------------------------
// AddInterpolant via mma.sync fp16 (baseline PTX; tcgen05 is sm_103a-gated).
// R16 = R15 GEMMs + prep collapse:
//   - layer 1 reads x0/x1 directly (fp32->fp16 in regs, register-staged
//     prefetch) — g_z and pack_z deleted
//   - all 4 weight transposes in ONE launch
// Tiles: BM=BN=64, NT=128 (2m x 2n warps of 32x32), 2-stage, 4 CTAs/SM.
// ---------------------------------------------------------------------------

constexpr int BATCH = 65536;
constexpr int SDIM  = 256;
constexpr int HID   = 1024;

constexpr int BM   = 64;
constexpr int BN   = 64;
constexpr int BKC  = 64;            // k per stage
constexpr int NT   = 128;           // 4 warps: 2 (m) x 2 (n)
constexpr int ATB  = BM * 128;      // 8192 B (tile: 64 rows x 128B)
constexpr int BTB  = BN * 128;      // 8192 B

// ---------------------------------------------------------------------------
// Scratch (static device memory)
// ---------------------------------------------------------------------------
__device__ __align__(256) __half g_hA [(size_t)BATCH * HID];
__device__ __align__(256) __half g_dA [(size_t)BATCH * HID];
__device__ __align__(256) __half g_hB [(size_t)BATCH * HID];
__device__ __align__(256) __half g_dB [(size_t)BATCH * HID];
__device__ __align__(256) __half g_w512h[HID];

// Transposed fp16 weights: Wt[n][k] = fp16(W[k][n])
__device__ __align__(256) __half g_wt1[(size_t)HID * 512];
__device__ __align__(256) __half g_wt2[(size_t)HID * HID];
__device__ __align__(256) __half g_wt3[(size_t)HID * HID];
__device__ __align__(256) __half g_wt4[(size_t)SDIM * HID];

// ---------------------------------------------------------------------------
// Helpers
// ---------------------------------------------------------------------------
__device__ __forceinline__ uint32_t smem_u32(const void* p) {
    uint32_t a;
    asm("{ .reg .u64 t; cvta.to.shared.u64 t, %1; cvt.u32.u64 %0, t; }"
        : "=r"(a) : "l"(p));
    return a;
}
__device__ __forceinline__ void cpasync16(uint32_t s, const void* g) {
    asm volatile("cp.async.cg.shared.global [%0], [%1], 16;"
                 :: "r"(s), "l"(g) : "memory");
}
__device__ __forceinline__ void cp_commit() {
    asm volatile("cp.async.commit_group;" ::: "memory");
}
template <int N>
__device__ __forceinline__ void cp_wait() {
    asm volatile("cp.async.wait_group %0;" :: "n"(N) : "memory");
}
__device__ __forceinline__ void ldsm4(uint32_t addr, uint32_t r[4]) {
    asm volatile("ldmatrix.sync.aligned.m8n8.x4.shared.b16 {%0,%1,%2,%3}, [%4];"
                 : "=r"(r[0]), "=r"(r[1]), "=r"(r[2]), "=r"(r[3]) : "r"(addr));
}
__device__ __forceinline__ void mma_f16(float c[4], const uint32_t a[4],
                                        const uint32_t b[2]) {
    asm("mma.sync.aligned.m16n8k16.row.col.f32.f16.f16.f32 "
        "{%0,%1,%2,%3}, {%4,%5,%6,%7}, {%8,%9}, {%0,%1,%2,%3};"
        : "+f"(c[0]), "+f"(c[1]), "+f"(c[2]), "+f"(c[3])
        : "r"(a[0]), "r"(a[1]), "r"(a[2]), "r"(a[3]), "r"(b[0]), "r"(b[1]));
}
__device__ __forceinline__ uint32_t swzoff(int row, int chunk) {
    return (uint32_t)(row * 128 + ((chunk ^ (row & 7)) << 4));
}
__device__ __forceinline__ uint32_t packh2(__half a, __half b) {
    __half2 t2(a, b);
    return *reinterpret_cast<uint32_t*>(&t2);
}
__device__ __forceinline__ uint32_t maskmul(uint32_t a, __half2 w) {
    const __half2 av = *reinterpret_cast<const __half2*>(&a);
    const __half2 m = __hgt2(av, __half2(__half(0.f), __half(0.f)));
    const __half2 r = __hmul2(m, w);
    return *reinterpret_cast<const uint32_t*>(&r);
}

// ---------------------------------------------------------------------------
// Prep: all 4 weight transposes in one launch (z selects the matrix)
// ---------------------------------------------------------------------------
__global__ void transpose_all_kernel(const float* __restrict__ W1,
                                     const float* __restrict__ W2,
                                     const float* __restrict__ W3,
                                     const float* __restrict__ W4,
                                     __half* __restrict__ wt1,
                                     __half* __restrict__ wt2,
                                     __half* __restrict__ wt3,
                                     __half* __restrict__ wt4) {
    __shared__ __half tile[32][40];
    const float* W;
    __half* wt;
    int K, N;
    switch (blockIdx.z) {
        case 0: W = W1; wt = wt1; K = 512;  N = HID;  break;
        case 1: W = W2; wt = wt2; K = HID;  N = HID;  break;
        case 2: W = W3; wt = wt3; K = HID;  N = HID;  break;
        default: W = W4; wt = wt4; K = HID; N = SDIM; break;
    }
    const int bx = blockIdx.x * 32;   // n
    const int by = blockIdx.y * 32;   // k
    if (bx >= N || by >= K) return;
    const int tx = threadIdx.x & 31;
    const int ty = threadIdx.x >> 5;
#pragma unroll
    for (int i = 0; i < 32; i += 8)
        tile[ty + i][tx] = __float2half_rn(W[(size_t)(by + ty + i) * N + bx + tx]);
    __syncthreads();
#pragma unroll
    for (int i = 0; i < 32; i += 8)
        wt[(size_t)(bx + ty + i) * K + by + tx] = tile[tx][ty + i];
}

__global__ void pack_w512_kernel(const float* __restrict__ W1row) {
    int id = blockIdx.x * blockDim.x + threadIdx.x;
    if (id < HID) g_w512h[id] = __float2half_rn(W1row[id]);
}

// ---------------------------------------------------------------------------
// Layer-1 kernel: reads x0/x1 directly (no g_z). A converted in registers;
// B (weights) via cp.async 2-stage. NC = 8 chunks over K=512.
// ---------------------------------------------------------------------------
__global__ __launch_bounds__(NT, 4)
void layer1_kernel(const float* __restrict__ x0, const float* __restrict__ x1,
                   const __half* __restrict__ Bw, const float* __restrict__ bias,
                   const float* __restrict__ w512, const float* __restrict__ t,
                   __half* __restrict__ oh) {
    extern __shared__ __align__(128) char smem[];
    constexpr int NC = 8;
    constexpr int STAGE = ATB + BTB;   // 16KB
    constexpr int OFF_B = ATB;

    const int tid  = threadIdx.x;
    const int warp = tid >> 5;
    const int lane = tid & 31;
    const int wm = (warp & 1) * 32;
    const int wn = (warp >> 1) * 32;
    const int row0 = blockIdx.y * BM;
    const int n0   = blockIdx.x * BN;

    const uint32_t sb0 = smem_u32(smem);
    const char* gBw = (const char*)(Bw + (size_t)n0 * 512);

    // per-thread A-loader coords (4 iters of 16B)
    int lrow[4], lseg[4];
#pragma unroll
    for (int i = 0; i < 4; ++i) {
        const int sid = i * NT + tid;
        lrow[i] = sid >> 3;
        lseg[i] = sid & 7;
    }

    float4 rA[4][2];   // staging for one chunk (8 floats per iter)

    auto ldA = [&](int c) {
        const float* src = (c < 4) ? x0 : x1;
        const int koff = (c & 3) * 64;
#pragma unroll
        for (int i = 0; i < 4; ++i) {
            const float* p = src + (size_t)(row0 + lrow[i]) * SDIM + koff + lseg[i] * 8;
            rA[i][0] = *(const float4*)p;
            rA[i][1] = *(const float4*)(p + 4);
        }
    };
    auto stsA = [&](int c) {
        const uint32_t base = sb0 + (c & 1) * STAGE;
#pragma unroll
        for (int i = 0; i < 4; ++i) {
            uint4 v;
            v.x = packh2(__float2half_rn(rA[i][0].x), __float2half_rn(rA[i][0].y));
            v.y = packh2(__float2half_rn(rA[i][0].z), __float2half_rn(rA[i][0].w));
            v.z = packh2(__float2half_rn(rA[i][1].x), __float2half_rn(rA[i][1].y));
            v.w = packh2(__float2half_rn(rA[i][1].z), __float2half_rn(rA[i][1].w));
            const uint32_t so = swzoff(lrow[i], lseg[i]);
            asm volatile("st.shared.v4.b32 [%0], {%1,%2,%3,%4};"
                         :: "r"(base + so), "r"(v.x), "r"(v.y), "r"(v.z), "r"(v.w)
                         : "memory");
        }
    };
    auto issueB = [&](int c) {
        const uint32_t base = sb0 + (c & 1) * STAGE + OFF_B;
        const size_t kb = (size_t)c * (BKC * 2);
#pragma unroll
        for (int i = 0; i < 4; ++i) {
            const uint32_t so = swzoff(lrow[i], lseg[i]);
            cpasync16(base + so, gBw + (size_t)lrow[i] * (512 * 2) + kb + lseg[i] * 16);
        }
        cp_commit();
    };

    float accV[2][4][4];
#pragma unroll
    for (int mt = 0; mt < 2; ++mt)
#pragma unroll
        for (int nt = 0; nt < 4; ++nt)
#pragma unroll
            for (int j = 0; j < 4; ++j) accV[mt][nt][j] = 0.f;

    // prologue
    ldA(0); stsA(0);
    issueB(0);
    ldA(1);

    const int ag = lane >> 3;
    const int arow0 = wm + (ag & 1) * 8 + (lane & 7);
    const int acb = ag >> 1;
    const int brow0 = wn + ((lane >> 3) >= 2 ? 8 : 0) + (lane & 7);
    const int bcb = (lane >> 3) & 1;

#pragma unroll 1
    for (int c = 0; c < NC; ++c) {
        cp_wait<0>();
        __syncthreads();
        if (c + 1 < NC) { issueB(c + 1); stsA(c + 1); }
        if (c + 2 < NC) ldA(c + 2);

        const uint32_t base = sb0 + (c & 1) * STAGE;
#pragma unroll
        for (int ks = 0; ks < 4; ++ks) {
            uint32_t bw[4][2];
#pragma unroll
            for (int np = 0; np < 2; ++np) {
                const uint32_t off = swzoff(brow0 + np * 16, bcb + 2 * ks);
                uint32_t r[4];
                ldsm4(base + OFF_B + off, r);
                bw[np * 2][0] = r[0]; bw[np * 2][1] = r[1];
                bw[np * 2 + 1][0] = r[2]; bw[np * 2 + 1][1] = r[3];
            }
            uint32_t av[2][4];
#pragma unroll
            for (int mt = 0; mt < 2; ++mt) {
                const uint32_t off = swzoff(arow0 + mt * 16, acb + 2 * ks);
                ldsm4(base + off, av[mt]);
            }
#pragma unroll
            for (int mt = 0; mt < 2; ++mt)
#pragma unroll
                for (int nt = 0; nt < 4; ++nt)
                    mma_f16(accV[mt][nt], av[mt], bw[nt]);
        }
    }
    __syncthreads();

    // epilogue (MODE 0)
    const int q2 = 2 * (lane & 3);
#pragma unroll
    for (int mt = 0; mt < 2; ++mt) {
#pragma unroll
        for (int nt = 0; nt < 4; ++nt) {
            const int col = n0 + wn + nt * 8 + q2;
            const float2 bv = *(const float2*)&bias[col];
            const float2 wv = *(const float2*)&w512[col];
#pragma unroll
            for (int cp = 0; cp < 2; ++cp) {
                const int row = row0 + wm + mt * 16 + (lane >> 2) + cp * 8;
                const float tv = t[row];
                const float pre0 = accV[mt][nt][cp * 2 + 0] + tv * wv.x + bv.x;
                const float pre1 = accV[mt][nt][cp * 2 + 1] + tv * wv.y + bv.y;
                const __half h0 = __float2half_rn(fmaxf(pre0, 0.f));
                const __half h1 = __float2half_rn(fmaxf(pre1, 0.f));
                *(uint32_t*)&oh[(size_t)row * HID + col] = packh2(h0, h1);
            }
        }
    }
}

// ---------------------------------------------------------------------------
// GEMM kernel for layers 2-4 (R15 verbatim). MODE: 1=mid, 2=layer4+combine.
// TG: tangent stream from gmem. DFLY: synthesize tangent from w512h.
// ---------------------------------------------------------------------------
template <int MODE, int NC, bool TG, bool DFLY, int LDA, int LDB>
__global__ __launch_bounds__(NT, 4)
void gemmf_kernel(const __half* __restrict__ Aa, const __half* __restrict__ Ad,
                  const __half* __restrict__ Bw,
                  const float* __restrict__ bias,
                  const float* __restrict__ p0, const float* __restrict__ p1,
                  const float* __restrict__ p2,
                  __half* __restrict__ oh, __half* __restrict__ od,
                  float* __restrict__ out) {
    extern __shared__ __align__(128) char smem[];
    constexpr bool COMPD = TG || DFLY;
    constexpr int NA = TG ? 2 : 1;
    constexpr int STAGE = NA * ATB + BTB;
    constexpr int OFF_B = NA * ATB;

    const int tid  = threadIdx.x;
    const int warp = tid >> 5;
    const int lane = tid & 31;
    const int wm = (warp & 1) * 32;
    const int wn = (warp >> 1) * 32;
    const int row0 = blockIdx.y * BM;
    const int n0   = blockIdx.x * BN;

    const uint32_t sb0 = smem_u32(smem);

    const char* gAa = (const char*)(Aa + (size_t)row0 * LDA);
    const char* gAd = TG ? (const char*)(Ad + (size_t)row0 * LDA) : nullptr;
    const char* gBw = (const char*)(Bw + (size_t)n0 * LDB);

    auto issue = [&](int c) {
        const uint32_t base = sb0 + (c & 1) * STAGE;
        const size_t kb = (size_t)c * (BKC * 2);
#pragma unroll
        for (int i = 0; i < 4; ++i) {
            const int sid = i * NT + tid;
            const int row = sid >> 3;
            const int seg = sid & 7;
            const uint32_t so = swzoff(row, seg);
            const size_t goA = (size_t)row * (LDA * 2) + kb + seg * 16;
            const size_t goB = (size_t)row * (LDB * 2) + kb + seg * 16;
            cpasync16(base + so, gAa + goA);
            if (TG) cpasync16(base + ATB + so, gAd + goA);
            cpasync16(base + OFF_B + so, gBw + goB);
        }
        cp_commit();
    };

    float accV[2][4][4];
    float accD[2][4][4];
#pragma unroll
    for (int mt = 0; mt < 2; ++mt)
#pragma unroll
        for (int nt = 0; nt < 4; ++nt)
#pragma unroll
            for (int j = 0; j < 4; ++j) { accV[mt][nt][j] = 0.f; if (COMPD) accD[mt][nt][j] = 0.f; }

    issue(0);

    const int ag = lane >> 3;
    const int arow0 = wm + (ag & 1) * 8 + (lane & 7);
    const int acb = ag >> 1;
    const int brow0 = wn + ((lane >> 3) >= 2 ? 8 : 0) + (lane & 7);
    const int bcb = (lane >> 3) & 1;
    const __half2* w512p = DFLY ? (const __half2*)g_w512h : nullptr;

#pragma unroll 1
    for (int c = 0; c < NC; ++c) {
        cp_wait<0>();
        __syncthreads();
        if (c + 1 < NC) issue(c + 1);

        const uint32_t base = sb0 + (c & 1) * STAGE;
#pragma unroll
        for (int ks = 0; ks < 4; ++ks) {
            uint32_t bw[4][2];
#pragma unroll
            for (int np = 0; np < 2; ++np) {
                const uint32_t off = swzoff(brow0 + np * 16, bcb + 2 * ks);
                uint32_t r[4];
                ldsm4(base + OFF_B + off, r);
                bw[np * 2][0] = r[0]; bw[np * 2][1] = r[1];
                bw[np * 2 + 1][0] = r[2]; bw[np * 2 + 1][1] = r[3];
            }
            __half2 w01, w89;
            if (DFLY) {
                const int kb2 = c * BKC + ks * 16;
                w01 = w512p[(kb2 >> 1) + (lane & 3)];
                w89 = w512p[((kb2 + 8) >> 1) + (lane & 3)];
            }
            uint32_t av[2][4], ad[2][4];
#pragma unroll
            for (int mt = 0; mt < 2; ++mt) {
                const uint32_t off = swzoff(arow0 + mt * 16, acb + 2 * ks);
                ldsm4(base + off, av[mt]);
                if (TG) ldsm4(base + ATB + off, ad[mt]);
                if (DFLY) {
                    ad[mt][0] = maskmul(av[mt][0], w01);
                    ad[mt][1] = maskmul(av[mt][1], w01);
                    ad[mt][2] = maskmul(av[mt][2], w89);
                    ad[mt][3] = maskmul(av[mt][3], w89);
                }
            }
#pragma unroll
            for (int mt = 0; mt < 2; ++mt)
#pragma unroll
                for (int nt = 0; nt < 4; ++nt) {
                    mma_f16(accV[mt][nt], av[mt], bw[nt]);
                    if (COMPD) mma_f16(accD[mt][nt], ad[mt], bw[nt]);
                }
        }
    }
    __syncthreads();

    // ---- Epilogue ----
    const int q2 = 2 * (lane & 3);
#pragma unroll
    for (int mt = 0; mt < 2; ++mt) {
#pragma unroll
        for (int nt = 0; nt < 4; ++nt) {
            const int col = n0 + wn + nt * 8 + q2;
            const float2 bv = *(const float2*)&bias[col];
#pragma unroll
            for (int cp = 0; cp < 2; ++cp) {
                const int row = row0 + wm + mt * 16 + (lane >> 2) + cp * 8;
                const float a0 = accV[mt][nt][cp * 2 + 0];
                const float a1 = accV[mt][nt][cp * 2 + 1];

                if (MODE == 1) {
                    const float pre0 = a0 + bv.x;
                    const float pre1 = a1 + bv.y;
                    const __half h0 = __float2half_rn(fmaxf(pre0, 0.f));
                    const __half h1 = __float2half_rn(fmaxf(pre1, 0.f));
                    const __half d0 = __float2half_rn(pre0 > 0.f ? accD[mt][nt][cp * 2 + 0] : 0.f);
                    const __half d1 = __float2half_rn(pre1 > 0.f ? accD[mt][nt][cp * 2 + 1] : 0.f);
                    const size_t o = (size_t)row * HID + col;
                    *(uint32_t*)&oh[o] = packh2(h0, h1);
                    *(uint32_t*)&od[o] = packh2(d0, d1);
                } else {
                    const float fnn0 = a0 + bv.x;
                    const float fnn1 = a1 + bv.y;
                    const float dt0 = accD[mt][nt][cp * 2 + 0];
                    const float dt1 = accD[mt][nt][cp * 2 + 1];
                    const float tv = p2[row];
                    const float tc = tv * (1.f - tv);
                    const float om2t = 1.f - 2.f * tv;
                    const size_t xo = (size_t)row * SDIM + col;
                    const float2 x0v = *(const float2*)&p0[xo];
                    const float2 x1v = *(const float2*)&p1[xo];
                    float2 xt, dxt;
                    xt.x = (1.f - tv) * x0v.x + tv * x1v.x + tc * fnn0;
                    xt.y = (1.f - tv) * x0v.y + tv * x1v.y + tc * fnn1;
                    dxt.x = x1v.x - x0v.x + om2t * fnn0 + tc * dt0;
                    dxt.y = x1v.y - x0v.y + om2t * fnn1 + tc * dt1;
                    *(float2*)&out[xo] = xt;
                    *(float2*)&out[(size_t)BATCH * SDIM + xo] = dxt;
                }
            }
        }
    }
}

// ---------------------------------------------------------------------------
// Launch
// ---------------------------------------------------------------------------
extern "C" void kernel_launch(void* const* d_in, const int* in_sizes, int n_in,
                              void* d_out, int out_size) {
    (void)in_sizes; (void)n_in; (void)out_size;
    const float* x0 = (const float*)d_in[0];
    const float* x1 = (const float*)d_in[1];
    const float* t  = (const float*)d_in[2];
    const float* W1 = (const float*)d_in[3];
    const float* b1 = (const float*)d_in[4];
    const float* W2 = (const float*)d_in[5];
    const float* b2 = (const float*)d_in[6];
    const float* W3 = (const float*)d_in[7];
    const float* b3 = (const float*)d_in[8];
    const float* W4 = (const float*)d_in[9];
    const float* b4 = (const float*)d_in[10];
    float* out = (float*)d_out;

    __half *hA, *dA, *hB, *dB, *w1, *w2, *w3, *w4;
    cudaGetSymbolAddress((void**)&hA, g_hA); cudaGetSymbolAddress((void**)&dA, g_dA);
    cudaGetSymbolAddress((void**)&hB, g_hB); cudaGetSymbolAddress((void**)&dB, g_dB);
    cudaGetSymbolAddress((void**)&w1, g_wt1); cudaGetSymbolAddress((void**)&w2, g_wt2);
    cudaGetSymbolAddress((void**)&w3, g_wt3); cudaGetSymbolAddress((void**)&w4, g_wt4);

    constexpr int SM_L1   = 2 * (ATB + BTB);      // 32768
    constexpr int SM_NOTG = 2 * (ATB + BTB);      // 32768
    constexpr int SM_TG   = 2 * (2 * ATB + BTB);  // 49152

    cudaFuncSetAttribute(layer1_kernel,
                         cudaFuncAttributeMaxDynamicSharedMemorySize, SM_L1);
    cudaFuncSetAttribute(gemmf_kernel<1, 16, false, true, 1024, 1024>,
                         cudaFuncAttributeMaxDynamicSharedMemorySize, SM_NOTG);
    cudaFuncSetAttribute(gemmf_kernel<1, 16, true, false, 1024, 1024>,
                         cudaFuncAttributeMaxDynamicSharedMemorySize, SM_TG);
    cudaFuncSetAttribute(gemmf_kernel<2, 16, true, false, 1024, 1024>,
                         cudaFuncAttributeMaxDynamicSharedMemorySize, SM_TG);

    // ---- prep: one transpose launch covering W1..W4, plus w512 pack ----
    {
        dim3 g(HID / 32, HID / 32, 4);   // max dims; kernel guards per-z bounds
        transpose_all_kernel<<<g, 256>>>(W1, W2, W3, W4, w1, w2, w3, w4);
    }
    pack_w512_kernel<<<4, 256>>>(W1 + (size_t)512 * HID);

    dim3 blk(NT);
    dim3 grid_hid(HID / BN, BATCH / BM);   // (16, 1024)
    dim3 grid_out(SDIM / BN, BATCH / BM);  // (4, 1024)

    // layer 1: direct x0/x1 read, h only (tangent synthesized in L2)
    layer1_kernel<<<grid_hid, blk, SM_L1>>>(
        x0, x1, w1, b1, W1 + (size_t)512 * HID, t, hA);

    // layer 2: A -> B, tangent on the fly from w512h
    gemmf_kernel<1, 16, false, true, 1024, 1024><<<grid_hid, blk, SM_NOTG>>>(
        hA, nullptr, w2, b2,
        nullptr, nullptr, nullptr,
        hB, dB, nullptr);

    // layer 3: B -> A
    gemmf_kernel<1, 16, true, false, 1024, 1024><<<grid_hid, blk, SM_TG>>>(
        hB, dB, w3, b3,
        nullptr, nullptr, nullptr,
        hA, dA, nullptr);

    // layer 4 + interpolant combine
    gemmf_kernel<2, 16, true, false, 1024, 1024><<<grid_out, blk, SM_TG>>>(
        hA, dA, w4, b4,
        x0, x1, t,
        nullptr, nullptr, out);
}

// round 17
// speedup vs baseline: 1.0686x; 1.0686x over previous
#include <cuda_runtime.h>
#include <cuda_fp16.h>
#include <cstdint>
#include <cstddef>

// ---------------------------------------------------------------------------
// AddInterpolant via mma.sync fp16 (baseline PTX; tcgen05 is sm_103a-gated).
// R17 = R15 (best: 1614us) + merged single-launch weight transpose.
// Tiles: BM=BN=64, NT=128 (2m x 2n warps of 32x32), 2-stage, 4 CTAs/SM.
// Value = a*w; tangent = d*w (L2 synthesizes d from w512h on the fly).
// ---------------------------------------------------------------------------

constexpr int BATCH = 65536;
constexpr int SDIM  = 256;
constexpr int HID   = 1024;

constexpr int BM   = 64;
constexpr int BN   = 64;
constexpr int BKC  = 64;            // k per stage
constexpr int NT   = 128;           // 4 warps: 2 (m) x 2 (n)
constexpr int ATB  = BM * 128;      // 8192 B (tile: 64 rows x 128B)
constexpr int BTB  = BN * 128;      // 8192 B

// ---------------------------------------------------------------------------
// Scratch (static device memory)
// ---------------------------------------------------------------------------
__device__ __align__(256) __half g_z  [(size_t)BATCH * 512];
__device__ __align__(256) __half g_hA [(size_t)BATCH * HID];
__device__ __align__(256) __half g_dA [(size_t)BATCH * HID];
__device__ __align__(256) __half g_hB [(size_t)BATCH * HID];
__device__ __align__(256) __half g_dB [(size_t)BATCH * HID];
__device__ __align__(256) __half g_w512h[HID];

// Transposed fp16 weights: Wt[n][k] = fp16(W[k][n])
__device__ __align__(256) __half g_wt1[(size_t)HID * 512];
__device__ __align__(256) __half g_wt2[(size_t)HID * HID];
__device__ __align__(256) __half g_wt3[(size_t)HID * HID];
__device__ __align__(256) __half g_wt4[(size_t)SDIM * HID];

// ---------------------------------------------------------------------------
// Helpers
// ---------------------------------------------------------------------------
__device__ __forceinline__ uint32_t smem_u32(const void* p) {
    uint32_t a;
    asm("{ .reg .u64 t; cvta.to.shared.u64 t, %1; cvt.u32.u64 %0, t; }"
        : "=r"(a) : "l"(p));
    return a;
}
__device__ __forceinline__ void cpasync16(uint32_t s, const void* g) {
    asm volatile("cp.async.cg.shared.global [%0], [%1], 16;"
                 :: "r"(s), "l"(g) : "memory");
}
__device__ __forceinline__ void cp_commit() {
    asm volatile("cp.async.commit_group;" ::: "memory");
}
template <int N>
__device__ __forceinline__ void cp_wait() {
    asm volatile("cp.async.wait_group %0;" :: "n"(N) : "memory");
}
__device__ __forceinline__ void ldsm4(uint32_t addr, uint32_t r[4]) {
    asm volatile("ldmatrix.sync.aligned.m8n8.x4.shared.b16 {%0,%1,%2,%3}, [%4];"
                 : "=r"(r[0]), "=r"(r[1]), "=r"(r[2]), "=r"(r[3]) : "r"(addr));
}
__device__ __forceinline__ void mma_f16(float c[4], const uint32_t a[4],
                                        const uint32_t b[2]) {
    asm("mma.sync.aligned.m16n8k16.row.col.f32.f16.f16.f32 "
        "{%0,%1,%2,%3}, {%4,%5,%6,%7}, {%8,%9}, {%0,%1,%2,%3};"
        : "+f"(c[0]), "+f"(c[1]), "+f"(c[2]), "+f"(c[3])
        : "r"(a[0]), "r"(a[1]), "r"(a[2]), "r"(a[3]), "r"(b[0]), "r"(b[1]));
}
__device__ __forceinline__ uint32_t swzoff(int row, int chunk) {
    return (uint32_t)(row * 128 + ((chunk ^ (row & 7)) << 4));
}
__device__ __forceinline__ uint32_t packh2(__half a, __half b) {
    __half2 t2(a, b);
    return *reinterpret_cast<uint32_t*>(&t2);
}
__device__ __forceinline__ uint32_t maskmul(uint32_t a, __half2 w) {
    const __half2 av = *reinterpret_cast<const __half2*>(&a);
    const __half2 m = __hgt2(av, __half2(__half(0.f), __half(0.f)));
    const __half2 r = __hmul2(m, w);
    return *reinterpret_cast<const uint32_t*>(&r);
}

// ---------------------------------------------------------------------------
// Prep kernels
// ---------------------------------------------------------------------------
// All 4 weight transposes in one launch (z selects the matrix)
__global__ void transpose_all_kernel(const float* __restrict__ W1,
                                     const float* __restrict__ W2,
                                     const float* __restrict__ W3,
                                     const float* __restrict__ W4,
                                     __half* __restrict__ wt1,
                                     __half* __restrict__ wt2,
                                     __half* __restrict__ wt3,
                                     __half* __restrict__ wt4) {
    __shared__ __half tile[32][40];
    const float* W;
    __half* wt;
    int K, N;
    switch (blockIdx.z) {
        case 0: W = W1; wt = wt1; K = 512;  N = HID;  break;
        case 1: W = W2; wt = wt2; K = HID;  N = HID;  break;
        case 2: W = W3; wt = wt3; K = HID;  N = HID;  break;
        default: W = W4; wt = wt4; K = HID; N = SDIM; break;
    }
    const int bx = blockIdx.x * 32;   // n
    const int by = blockIdx.y * 32;   // k
    if (bx >= N || by >= K) return;
    const int tx = threadIdx.x & 31;
    const int ty = threadIdx.x >> 5;
#pragma unroll
    for (int i = 0; i < 32; i += 8)
        tile[ty + i][tx] = __float2half_rn(W[(size_t)(by + ty + i) * N + bx + tx]);
    __syncthreads();
#pragma unroll
    for (int i = 0; i < 32; i += 8)
        wt[(size_t)(bx + ty + i) * K + by + tx] = tile[tx][ty + i];
}

__global__ void pack_w512_kernel(const float* __restrict__ W1row) {
    int id = blockIdx.x * blockDim.x + threadIdx.x;
    if (id < HID) g_w512h[id] = __float2half_rn(W1row[id]);
}

__global__ void pack_z_kernel(const float* __restrict__ x0, const float* __restrict__ x1) {
    int id = blockIdx.x * blockDim.x + threadIdx.x;
    if (id >= BATCH * SDIM / 4) return;
    int b = id / (SDIM / 4), q = id % (SDIM / 4);
    const float4 v0 = *(const float4*)&x0[(size_t)b * SDIM + q * 4];
    const float4 v1 = *(const float4*)&x1[(size_t)b * SDIM + q * 4];
    uint2 o0 = make_uint2(packh2(__float2half_rn(v0.x), __float2half_rn(v0.y)),
                          packh2(__float2half_rn(v0.z), __float2half_rn(v0.w)));
    uint2 o1 = make_uint2(packh2(__float2half_rn(v1.x), __float2half_rn(v1.y)),
                          packh2(__float2half_rn(v1.z), __float2half_rn(v1.w)));
    *(uint2*)&g_z[(size_t)b * 512 + q * 4]       = o0;
    *(uint2*)&g_z[(size_t)b * 512 + 256 + q * 4] = o1;
}

// ---------------------------------------------------------------------------
// GEMM kernel. MODE: 0=layer1, 1=mid, 2=layer4+combine.
// TG: tangent stream from gmem. DFLY: synthesize tangent from w512h.
// Warp layout: 2m x 2n; warp tile 32x32; 2-stage pipeline; 4 CTA/SM.
// ---------------------------------------------------------------------------
template <int MODE, int NC, bool TG, bool DFLY, int LDA, int LDB>
__global__ __launch_bounds__(NT, 4)
void gemmf_kernel(const __half* __restrict__ Aa, const __half* __restrict__ Ad,
                  const __half* __restrict__ Bw,
                  const float* __restrict__ bias,
                  const float* __restrict__ p0, const float* __restrict__ p1,
                  const float* __restrict__ p2,
                  __half* __restrict__ oh, __half* __restrict__ od,
                  float* __restrict__ out) {
    extern __shared__ __align__(128) char smem[];
    constexpr bool COMPD = TG || DFLY;
    constexpr int NA = TG ? 2 : 1;
    constexpr int STAGE = NA * ATB + BTB;       // 24KB (TG) / 16KB
    constexpr int OFF_B = NA * ATB;

    const int tid  = threadIdx.x;
    const int warp = tid >> 5;
    const int lane = tid & 31;
    const int wm = (warp & 1) * 32;        // 2 warps along m
    const int wn = (warp >> 1) * 32;       // 2 warps along n
    const int row0 = blockIdx.y * BM;
    const int n0   = blockIdx.x * BN;

    const uint32_t sb0 = smem_u32(smem);

    const char* gAa = (const char*)(Aa + (size_t)row0 * LDA);
    const char* gAd = TG ? (const char*)(Ad + (size_t)row0 * LDA) : nullptr;
    const char* gBw = (const char*)(Bw + (size_t)n0 * LDB);

    auto issue = [&](int c) {
        const uint32_t base = sb0 + (c & 1) * STAGE;
        const size_t kb = (size_t)c * (BKC * 2);
#pragma unroll
        for (int i = 0; i < 4; ++i) {
            const int sid = i * NT + tid;
            const int row = sid >> 3;
            const int seg = sid & 7;
            const uint32_t so = swzoff(row, seg);
            const size_t goA = (size_t)row * (LDA * 2) + kb + seg * 16;
            const size_t goB = (size_t)row * (LDB * 2) + kb + seg * 16;
            cpasync16(base + so, gAa + goA);
            if (TG) cpasync16(base + ATB + so, gAd + goA);
            cpasync16(base + OFF_B + so, gBw + goB);
        }
        cp_commit();
    };

    float accV[2][4][4];
    float accD[2][4][4];
#pragma unroll
    for (int mt = 0; mt < 2; ++mt)
#pragma unroll
        for (int nt = 0; nt < 4; ++nt)
#pragma unroll
            for (int j = 0; j < 4; ++j) { accV[mt][nt][j] = 0.f; if (COMPD) accD[mt][nt][j] = 0.f; }

    issue(0);

    const int ag = lane >> 3;
    const int arow0 = wm + (ag & 1) * 8 + (lane & 7);
    const int acb = ag >> 1;
    const int brow0 = wn + ((lane >> 3) >= 2 ? 8 : 0) + (lane & 7);
    const int bcb = (lane >> 3) & 1;
    const __half2* w512p = DFLY ? (const __half2*)g_w512h : nullptr;

#pragma unroll 1
    for (int c = 0; c < NC; ++c) {
        cp_wait<0>();
        __syncthreads();
        if (c + 1 < NC) issue(c + 1);

        const uint32_t base = sb0 + (c & 1) * STAGE;
#pragma unroll
        for (int ks = 0; ks < 4; ++ks) {
            uint32_t bw[4][2];
#pragma unroll
            for (int np = 0; np < 2; ++np) {
                const uint32_t off = swzoff(brow0 + np * 16, bcb + 2 * ks);
                uint32_t r[4];
                ldsm4(base + OFF_B + off, r);
                bw[np * 2][0] = r[0]; bw[np * 2][1] = r[1];
                bw[np * 2 + 1][0] = r[2]; bw[np * 2 + 1][1] = r[3];
            }
            __half2 w01, w89;
            if (DFLY) {
                const int kb2 = c * BKC + ks * 16;
                w01 = w512p[(kb2 >> 1) + (lane & 3)];
                w89 = w512p[((kb2 + 8) >> 1) + (lane & 3)];
            }
            uint32_t av[2][4], ad[2][4];
#pragma unroll
            for (int mt = 0; mt < 2; ++mt) {
                const uint32_t off = swzoff(arow0 + mt * 16, acb + 2 * ks);
                ldsm4(base + off, av[mt]);
                if (TG) ldsm4(base + ATB + off, ad[mt]);
                if (DFLY) {
                    ad[mt][0] = maskmul(av[mt][0], w01);
                    ad[mt][1] = maskmul(av[mt][1], w01);
                    ad[mt][2] = maskmul(av[mt][2], w89);
                    ad[mt][3] = maskmul(av[mt][3], w89);
                }
            }
#pragma unroll
            for (int mt = 0; mt < 2; ++mt)
#pragma unroll
                for (int nt = 0; nt < 4; ++nt) {
                    mma_f16(accV[mt][nt], av[mt], bw[nt]);
                    if (COMPD) mma_f16(accD[mt][nt], ad[mt], bw[nt]);
                }
        }
    }
    __syncthreads();

    // ---- Epilogue ----
    const int q2 = 2 * (lane & 3);
#pragma unroll
    for (int mt = 0; mt < 2; ++mt) {
#pragma unroll
        for (int nt = 0; nt < 4; ++nt) {
            const int col = n0 + wn + nt * 8 + q2;
            const float2 bv = *(const float2*)&bias[col];
#pragma unroll
            for (int cp = 0; cp < 2; ++cp) {
                const int row = row0 + wm + mt * 16 + (lane >> 2) + cp * 8;
                const float a0 = accV[mt][nt][cp * 2 + 0];
                const float a1 = accV[mt][nt][cp * 2 + 1];

                if (MODE == 0) {
                    const float2 wv = *(const float2*)&p0[col];
                    const float tv = p1[row];
                    const float pre0 = a0 + tv * wv.x + bv.x;
                    const float pre1 = a1 + tv * wv.y + bv.y;
                    const __half h0 = __float2half_rn(fmaxf(pre0, 0.f));
                    const __half h1 = __float2half_rn(fmaxf(pre1, 0.f));
                    const size_t o = (size_t)row * HID + col;
                    *(uint32_t*)&oh[o] = packh2(h0, h1);
                } else if (MODE == 1) {
                    const float pre0 = a0 + bv.x;
                    const float pre1 = a1 + bv.y;
                    const __half h0 = __float2half_rn(fmaxf(pre0, 0.f));
                    const __half h1 = __float2half_rn(fmaxf(pre1, 0.f));
                    const __half d0 = __float2half_rn(pre0 > 0.f ? accD[mt][nt][cp * 2 + 0] : 0.f);
                    const __half d1 = __float2half_rn(pre1 > 0.f ? accD[mt][nt][cp * 2 + 1] : 0.f);
                    const size_t o = (size_t)row * HID + col;
                    *(uint32_t*)&oh[o] = packh2(h0, h1);
                    *(uint32_t*)&od[o] = packh2(d0, d1);
                } else {
                    const float fnn0 = a0 + bv.x;
                    const float fnn1 = a1 + bv.y;
                    const float dt0 = accD[mt][nt][cp * 2 + 0];
                    const float dt1 = accD[mt][nt][cp * 2 + 1];
                    const float tv = p2[row];
                    const float tc = tv * (1.f - tv);
                    const float om2t = 1.f - 2.f * tv;
                    const size_t xo = (size_t)row * SDIM + col;
                    const float2 x0v = *(const float2*)&p0[xo];
                    const float2 x1v = *(const float2*)&p1[xo];
                    float2 xt, dxt;
                    xt.x = (1.f - tv) * x0v.x + tv * x1v.x + tc * fnn0;
                    xt.y = (1.f - tv) * x0v.y + tv * x1v.y + tc * fnn1;
                    dxt.x = x1v.x - x0v.x + om2t * fnn0 + tc * dt0;
                    dxt.y = x1v.y - x0v.y + om2t * fnn1 + tc * dt1;
                    *(float2*)&out[xo] = xt;
                    *(float2*)&out[(size_t)BATCH * SDIM + xo] = dxt;
                }
            }
        }
    }
}

// ---------------------------------------------------------------------------
// Launch
// ---------------------------------------------------------------------------
extern "C" void kernel_launch(void* const* d_in, const int* in_sizes, int n_in,
                              void* d_out, int out_size) {
    (void)in_sizes; (void)n_in; (void)out_size;
    const float* x0 = (const float*)d_in[0];
    const float* x1 = (const float*)d_in[1];
    const float* t  = (const float*)d_in[2];
    const float* W1 = (const float*)d_in[3];
    const float* b1 = (const float*)d_in[4];
    const float* W2 = (const float*)d_in[5];
    const float* b2 = (const float*)d_in[6];
    const float* W3 = (const float*)d_in[7];
    const float* b3 = (const float*)d_in[8];
    const float* W4 = (const float*)d_in[9];
    const float* b4 = (const float*)d_in[10];
    float* out = (float*)d_out;

    __half *z, *hA, *dA, *hB, *dB, *w1, *w2, *w3, *w4;
    cudaGetSymbolAddress((void**)&z, g_z);
    cudaGetSymbolAddress((void**)&hA, g_hA); cudaGetSymbolAddress((void**)&dA, g_dA);
    cudaGetSymbolAddress((void**)&hB, g_hB); cudaGetSymbolAddress((void**)&dB, g_dB);
    cudaGetSymbolAddress((void**)&w1, g_wt1); cudaGetSymbolAddress((void**)&w2, g_wt2);
    cudaGetSymbolAddress((void**)&w3, g_wt3); cudaGetSymbolAddress((void**)&w4, g_wt4);

    constexpr int SM_NOTG = 2 * (ATB + BTB);      // 32768
    constexpr int SM_TG   = 2 * (2 * ATB + BTB);  // 49152

    cudaFuncSetAttribute(gemmf_kernel<0, 8, false, false, 512, 512>,
                         cudaFuncAttributeMaxDynamicSharedMemorySize, SM_NOTG);
    cudaFuncSetAttribute(gemmf_kernel<1, 16, false, true, 1024, 1024>,
                         cudaFuncAttributeMaxDynamicSharedMemorySize, SM_NOTG);
    cudaFuncSetAttribute(gemmf_kernel<1, 16, true, false, 1024, 1024>,
                         cudaFuncAttributeMaxDynamicSharedMemorySize, SM_TG);
    cudaFuncSetAttribute(gemmf_kernel<2, 16, true, false, 1024, 1024>,
                         cudaFuncAttributeMaxDynamicSharedMemorySize, SM_TG);

    // ---- prep ----
    pack_z_kernel<<<(BATCH * SDIM / 4 + 255) / 256, 256>>>(x0, x1);
    {
        dim3 g(HID / 32, HID / 32, 4);   // max dims; kernel guards per-z bounds
        transpose_all_kernel<<<g, 256>>>(W1, W2, W3, W4, w1, w2, w3, w4);
    }
    pack_w512_kernel<<<4, 256>>>(W1 + (size_t)512 * HID);

    dim3 blk(NT);
    dim3 grid_hid(HID / BN, BATCH / BM);   // (16, 1024)
    dim3 grid_out(SDIM / BN, BATCH / BM);  // (4, 1024)

    // layer 1: value GEMM over z; h only (tangent synthesized in L2)
    gemmf_kernel<0, 8, false, false, 512, 512><<<grid_hid, blk, SM_NOTG>>>(
        z, nullptr, w1, b1,
        W1 + (size_t)512 * HID, t, nullptr,
        hA, nullptr, nullptr);

    // layer 2: A -> B, tangent on the fly from w512h
    gemmf_kernel<1, 16, false, true, 1024, 1024><<<grid_hid, blk, SM_NOTG>>>(
        hA, nullptr, w2, b2,
        nullptr, nullptr, nullptr,
        hB, dB, nullptr);

    // layer 3: B -> A
    gemmf_kernel<1, 16, true, false, 1024, 1024><<<grid_hid, blk, SM_TG>>>(
        hB, dB, w3, b3,
        nullptr, nullptr, nullptr,
        hA, dA, nullptr);

    // layer 4 + interpolant combine
    gemmf_kernel<2, 16, true, false, 1024, 1024><<<grid_out, blk, SM_TG>>>(
        hA, dA, w4, b4,
        x0, x1, t,
        nullptr, nullptr, out);
}